// round 2
// baseline (speedup 1.0000x reference)
#include <cuda_runtime.h>
#include <math.h>
#include <float.h>

#define H 256
#define G_ 256
#define H2 512
#define E_MAX 524288

// ---------------- scratch (static device globals; no allocation) ----------------
__device__ float    d_att[E_MAX];      // att_raw per edge (post leaky + bonus)
__device__ float    d_sumtok[G_ * H];  // segment sum of edge_tokens
__device__ int      d_cnt[G_];         // edges per graph
__device__ unsigned d_gmax[G_];        // ordered-uint encoded segment max
__device__ float    d_gsum[G_];        // segment sum of masked exp
__device__ float    d_u[H];            // att_vec @ W_edge
__device__ float    d_v[H];            // att_vec @ W_query
__device__ float    d_qatt[G_];        // question_tokens @ v

// monotone float<->uint map for atomicMax on floats (handles negatives)
__device__ __forceinline__ unsigned f2ord(float f) {
    unsigned b = __float_as_uint(f);
    return (b & 0x80000000u) ? ~b : (b | 0x80000000u);
}
__device__ __forceinline__ float ord2f(unsigned u) {
    unsigned b = (u & 0x80000000u) ? (u & 0x7fffffffu) : ~u;
    return __uint_as_float(b);
}

// ---------------- K0: zero/init scratch ----------------
__global__ void k_init() {
    int i = blockIdx.x * blockDim.x + threadIdx.x;
    if (i < G_ * H) d_sumtok[i] = 0.0f;
    if (i < G_) {
        d_cnt[i] = 0;
        d_gmax[i] = 0u;      // smallest ordered key
        d_gsum[i] = 0.0f;
    }
}

// ---------------- K1: u = att_vec @ W_edge, v = att_vec @ W_query ----------------
__global__ void k_uv(const float* __restrict__ We, const float* __restrict__ Wq,
                     const float* __restrict__ av) {
    __shared__ float sa[H];
    int k = threadIdx.x;
    sa[k] = av[k];
    __syncthreads();
    float u = 0.0f, v = 0.0f;
    #pragma unroll 4
    for (int j = 0; j < H; j++) {
        float a = sa[j];
        u = fmaf(a, We[j * H + k], u);
        v = fmaf(a, Wq[j * H + k], v);
    }
    d_u[k] = u;
    d_v[k] = v;
}

// ---------------- K1b: qatt[g] = question_tokens[g] . v ----------------
__global__ void k_qatt(const float* __restrict__ qt) {
    int g = blockIdx.x, lane = threadIdx.x;
    const float4* q4 = (const float4*)(qt + g * H);
    const float4* v4 = (const float4*)d_v;
    float4 a = q4[lane], b = q4[lane + 32];
    float4 va = v4[lane], vb = v4[lane + 32];
    float s = a.x*va.x + a.y*va.y + a.z*va.z + a.w*va.w
            + b.x*vb.x + b.y*vb.y + b.z*vb.z + b.w*vb.w;
    #pragma unroll
    for (int o = 16; o; o >>= 1) s += __shfl_xor_sync(0xffffffffu, s, o);
    if (lane == 0) d_qatt[g] = s;
}

// ---------------- K2: main streaming pass ----------------
// warp processes a contiguous range of edges; per edge: dot(row, u), leaky,
// bonus; run-local accumulation of segment max / count / column sums.
__global__ void k_main(const float* __restrict__ et, const int* __restrict__ batch,
                       const int* __restrict__ sel, int E, int epw) {
    int wid  = (blockIdx.x * blockDim.x + threadIdx.x) >> 5;
    int lane = threadIdx.x & 31;
    int start = wid * epw;
    if (start >= E) return;
    int end = min(E, start + epw);

    const float4* u4 = (const float4*)d_u;
    float4 ua = u4[lane], ub = u4[lane + 32];

    int   cur_g   = batch[start];
    float4 cs0 = make_float4(0.f, 0.f, 0.f, 0.f);
    float4 cs1 = make_float4(0.f, 0.f, 0.f, 0.f);
    int   run_cnt = 0;
    float run_max = -3.0e38f;

    // prefetch first edge
    const float4* row = (const float4*)(et + (size_t)start * H);
    float4 a = row[lane], b = row[lane + 32];

    for (int e = start; e < end; e++) {
        // prefetch next edge
        float4 na, nb;
        if (e + 1 < end) {
            const float4* nrow = (const float4*)(et + (size_t)(e + 1) * H);
            na = nrow[lane]; nb = nrow[lane + 32];
        }
        int g = batch[e];
        if (g != cur_g) {
            // flush run
            float* st = d_sumtok + cur_g * H;
            atomicAdd(st + 4*lane + 0,       cs0.x);
            atomicAdd(st + 4*lane + 1,       cs0.y);
            atomicAdd(st + 4*lane + 2,       cs0.z);
            atomicAdd(st + 4*lane + 3,       cs0.w);
            atomicAdd(st + 128 + 4*lane + 0, cs1.x);
            atomicAdd(st + 128 + 4*lane + 1, cs1.y);
            atomicAdd(st + 128 + 4*lane + 2, cs1.z);
            atomicAdd(st + 128 + 4*lane + 3, cs1.w);
            if (lane == 0) {
                atomicAdd(&d_cnt[cur_g], run_cnt);
                atomicMax(&d_gmax[cur_g], f2ord(run_max));
            }
            cs0 = make_float4(0.f, 0.f, 0.f, 0.f);
            cs1 = make_float4(0.f, 0.f, 0.f, 0.f);
            run_cnt = 0; run_max = -3.0e38f; cur_g = g;
        }
        // accumulate column sums
        cs0.x += a.x; cs0.y += a.y; cs0.z += a.z; cs0.w += a.w;
        cs1.x += b.x; cs1.y += b.y; cs1.z += b.z; cs1.w += b.w;
        // dot with u
        float s = a.x*ua.x + a.y*ua.y + a.z*ua.z + a.w*ua.w
                + b.x*ub.x + b.y*ub.y + b.z*ub.z + b.w*ub.w;
        #pragma unroll
        for (int o = 16; o; o >>= 1) s += __shfl_xor_sync(0xffffffffu, s, o);
        float t = s + d_qatt[g];
        t = (t > 0.0f) ? t : 0.2f * t;               // LeakyReLU(0.2)
        if (sel[e] == 0) t += 0.5f;                  // frontier bonus on candidates
        run_max = fmaxf(run_max, t);
        run_cnt++;
        if (lane == 0) d_att[e] = t;
        a = na; b = nb;
    }
    // final flush
    {
        float* st = d_sumtok + cur_g * H;
        atomicAdd(st + 4*lane + 0,       cs0.x);
        atomicAdd(st + 4*lane + 1,       cs0.y);
        atomicAdd(st + 4*lane + 2,       cs0.z);
        atomicAdd(st + 4*lane + 3,       cs0.w);
        atomicAdd(st + 128 + 4*lane + 0, cs1.x);
        atomicAdd(st + 128 + 4*lane + 1, cs1.y);
        atomicAdd(st + 128 + 4*lane + 2, cs1.z);
        atomicAdd(st + 128 + 4*lane + 3, cs1.w);
        if (lane == 0) {
            atomicAdd(&d_cnt[cur_g], run_cnt);
            atomicMax(&d_gmax[cur_g], f2ord(run_max));
        }
    }
}

// ---------------- K3: per-graph sum of exp(att - max) over candidates ----------------
__global__ void k_expsum(const int* __restrict__ batch, const int* __restrict__ sel,
                         int E, int chunk) {
    int t = blockIdx.x * blockDim.x + threadIdx.x;
    int start = t * chunk;
    if (start >= E) return;
    int end = min(E, start + chunk);
    int cur_g = batch[start];
    float m = ord2f(d_gmax[cur_g]);
    float acc = 0.0f;
    for (int e = start; e < end; e++) {
        int g = batch[e];
        if (g != cur_g) {
            atomicAdd(&d_gsum[cur_g], acc);
            cur_g = g; m = ord2f(d_gmax[g]); acc = 0.0f;
        }
        if (sel[e] == 0) acc += expf(d_att[e] - m);
    }
    atomicAdd(&d_gsum[cur_g], acc);
}

// ---------------- K4: edge_logits ----------------
__global__ void k_logits(const int* __restrict__ batch, const int* __restrict__ sel,
                         float* __restrict__ out, int E) {
    int e = blockIdx.x * blockDim.x + threadIdx.x;
    if (e >= E) return;
    int g = batch[e];
    float m = ord2f(d_gmax[g]);
    float s = fmaxf(d_gsum[g], FLT_EPSILON);
    float p = (sel[e] == 0) ? expf(d_att[e] - m) / s : 0.0f;
    out[e] = logf(fmaxf(p, FLT_EPSILON));
}

// ---------------- K5: pooled GEMM + stop head (one block per graph) ----------------
__device__ __forceinline__ float breduce256(float v, volatile float* sred) {
    int lane = threadIdx.x & 31, w = threadIdx.x >> 5;
    #pragma unroll
    for (int o = 16; o; o >>= 1) v += __shfl_xor_sync(0xffffffffu, v, o);
    __syncthreads();
    if (lane == 0) sred[w] = v;
    __syncthreads();
    if (threadIdx.x < 32) {
        v = (threadIdx.x < 8) ? sred[threadIdx.x] : 0.0f;
        #pragma unroll
        for (int o = 4; o; o >>= 1) v += __shfl_xor_sync(0xffffffffu, v, o);
        if (threadIdx.x == 0) sred[0] = v;
    }
    __syncthreads();
    return sred[0];
}

__global__ void k_head(const float* __restrict__ qt, const float* __restrict__ We,
                       const float* __restrict__ lng, const float* __restrict__ lnb,
                       const float* __restrict__ W1, const float* __restrict__ b1,
                       const float* __restrict__ W2, const float* __restrict__ b2,
                       float* __restrict__ out_stop, float* __restrict__ out_pool) {
    __shared__ float spool[H];
    __shared__ float sxn[H2];
    __shared__ float sred[8];
    int g = blockIdx.x, j = threadIdx.x;

    spool[j] = d_sumtok[g * H + j];
    __syncthreads();

    float c = (float)max(d_cnt[g], 1);
    float acc = 0.0f;
    const float4* wr = (const float4*)(We + j * H);
    const float4* sp = (const float4*)spool;
    #pragma unroll 4
    for (int k = 0; k < H / 4; k++) {
        float4 w = wr[k], x = sp[k];
        acc = fmaf(w.x, x.x, acc); acc = fmaf(w.y, x.y, acc);
        acc = fmaf(w.z, x.z, acc); acc = fmaf(w.w, x.w, acc);
    }
    float p  = acc / c;
    float x0 = p;               // stop_input[j]
    float x1 = qt[g * H + j];   // stop_input[H+j]
    out_pool[g * H + j] = p;

    // LayerNorm over 512
    float tot = breduce256(x0 + x1, sred);
    float mu = tot * (1.0f / 512.0f);
    float d0 = x0 - mu, d1 = x1 - mu;
    float var = breduce256(d0 * d0 + d1 * d1, sred) * (1.0f / 512.0f);
    float inv = rsqrtf(var + 1e-5f);
    sxn[j]     = d0 * inv * lng[j]     + lnb[j];
    sxn[H + j] = d1 * inv * lng[H + j] + lnb[H + j];
    __syncthreads();

    // h1 = GELU(xn @ W1.T + b1)
    float h = b1[j];
    const float4* w1r = (const float4*)(W1 + j * H2);
    const float4* xn4 = (const float4*)sxn;
    #pragma unroll 4
    for (int k = 0; k < H2 / 4; k++) {
        float4 w = w1r[k], x = xn4[k];
        h = fmaf(w.x, x.x, h); h = fmaf(w.y, x.y, h);
        h = fmaf(w.z, x.z, h); h = fmaf(w.w, x.w, h);
    }
    h = 0.5f * h * (1.0f + erff(h * 0.70710678118654752f));   // exact GELU

    float st = breduce256(h * W2[j], sred);
    if (j == 0) out_stop[g] = st + b2[0];
}

// ---------------- launch ----------------
extern "C" void kernel_launch(void* const* d_in, const int* in_sizes, int n_in,
                              void* d_out, int out_size) {
    const float* edge_tokens     = (const float*)d_in[0];
    const float* question_tokens = (const float*)d_in[1];
    const int*   edge_batch      = (const int*)d_in[2];
    const int*   selected_mask   = (const int*)d_in[3];  // {0,1}; works for int32/f32 encodings
    const float* W_edge          = (const float*)d_in[4];
    const float* W_query         = (const float*)d_in[5];
    const float* att_vec         = (const float*)d_in[6];
    const float* ln_g            = (const float*)d_in[7];
    const float* ln_b            = (const float*)d_in[8];
    const float* W1              = (const float*)d_in[9];
    const float* b1              = (const float*)d_in[10];
    const float* W2              = (const float*)d_in[11];
    const float* b2              = (const float*)d_in[12];

    int E = in_sizes[2];
    float* out          = (float*)d_out;
    float* out_edge     = out;             // [E]
    float* out_stop     = out + E;         // [G]
    float* out_pool     = out + E + G_;    // [G, H]

    // K0: init scratch
    k_init<<<(G_ * H + 255) / 256, 256>>>();
    // K1: u, v
    k_uv<<<1, H>>>(W_edge, W_query, att_vec);
    // K1b: qatt
    k_qatt<<<G_, 32>>>(question_tokens);
    // K2: main streaming pass
    {
        int blocks = 512, threads = 256;
        int warps = blocks * threads / 32;
        int epw = (E + warps - 1) / warps;
        k_main<<<blocks, threads>>>(edge_tokens, edge_batch, selected_mask, E, epw);
    }
    // K3: exp sums
    {
        int chunk = 32;
        int nthreads = (E + chunk - 1) / chunk;
        k_expsum<<<(nthreads + 255) / 256, 256>>>(edge_batch, selected_mask, E, chunk);
    }
    // K4: edge logits
    k_logits<<<(E + 255) / 256, 256>>>(edge_batch, selected_mask, out_edge, E);
    // K5: pooled + stop head
    k_head<<<G_, H>>>(question_tokens, W_edge, ln_g, ln_b, W1, b1, W2, b2,
                      out_stop, out_pool);
}

// round 4
// speedup vs baseline: 1.3802x; 1.3802x over previous
#include <cuda_runtime.h>
#include <math.h>
#include <float.h>

#define H 256
#define G_ 256
#define H2 512
#define E_MAX 524288
#define GT 8                      // graphs per block in k_head
#define LOGEPS -15.942385152878742f   // logf(FLT_EPSILON)

// ---------------- scratch (static device globals; no allocation) ----------------
__device__ float    d_att[E_MAX];      // att_raw per edge (post leaky + bonus)
__device__ float    d_sumtok[G_ * H];  // segment sum of edge_tokens
__device__ int      d_cnt[G_];         // edges per graph
__device__ unsigned d_gmax[G_];        // ordered-uint encoded segment max
__device__ float    d_gsum[G_];        // segment sum of masked exp
__device__ float    d_u[H];            // att_vec @ W_edge
__device__ float    d_v[H];            // att_vec @ W_query
__device__ float    d_qatt[G_];        // question_tokens @ v

// monotone float<->uint map for atomicMax on floats (handles negatives)
__device__ __forceinline__ unsigned f2ord(float f) {
    unsigned b = __float_as_uint(f);
    return (b & 0x80000000u) ? ~b : (b | 0x80000000u);
}
__device__ __forceinline__ float ord2f(unsigned u) {
    unsigned b = (u & 0x80000000u) ? (u & 0x7fffffffu) : ~u;
    return __uint_as_float(b);
}

// ---------------- K1: u = att_vec @ W_edge, v = att_vec @ W_query (8 blocks) ----
__global__ void k_uv(const float* __restrict__ We, const float* __restrict__ Wq,
                     const float* __restrict__ av) {
    __shared__ float sa[H];
    __shared__ float ru[8][32], rv[8][32];
    int tx = threadIdx.x & 31, ty = threadIdx.x >> 5;
    sa[threadIdx.x] = av[threadIdx.x];
    __syncthreads();
    int col = blockIdx.x * 32 + tx;
    float u = 0.0f, v = 0.0f;
    #pragma unroll 4
    for (int j = ty; j < H; j += 8) {
        float a = sa[j];
        u = fmaf(a, We[j * H + col], u);
        v = fmaf(a, Wq[j * H + col], v);
    }
    ru[ty][tx] = u; rv[ty][tx] = v;
    __syncthreads();
    if (ty == 0) {
        float su = 0.0f, sv = 0.0f;
        #pragma unroll
        for (int r = 0; r < 8; r++) { su += ru[r][tx]; sv += rv[r][tx]; }
        d_u[col] = su; d_v[col] = sv;
    }
}

// ---------------- K1b: qatt[g] = question_tokens[g] . v   + scratch init ----------
__global__ void k_qatt(const float* __restrict__ qt) {
    int g = blockIdx.x, lane = threadIdx.x;
    // init scratch for this graph
    float4 z = make_float4(0.f, 0.f, 0.f, 0.f);
    ((float4*)d_sumtok)[g * 64 + lane]      = z;
    ((float4*)d_sumtok)[g * 64 + 32 + lane] = z;
    if (lane == 0) { d_cnt[g] = 0; d_gmax[g] = 0u; d_gsum[g] = 0.0f; }
    // dot
    const float4* q4 = (const float4*)(qt + g * H);
    const float4* v4 = (const float4*)d_v;
    float4 a = q4[lane], b = q4[lane + 32];
    float4 va = v4[lane], vb = v4[lane + 32];
    float s = a.x*va.x + a.y*va.y + a.z*va.z + a.w*va.w
            + b.x*vb.x + b.y*vb.y + b.z*vb.z + b.w*vb.w;
    #pragma unroll
    for (int o = 16; o; o >>= 1) s += __shfl_xor_sync(0xffffffffu, s, o);
    if (lane == 0) d_qatt[g] = s;
}

// ---------------- K2: main streaming pass (balanced grid, unroll-2) ----------------
__device__ __forceinline__ void flush_run(int cur_g, float4 cs0, float4 cs1,
                                          int run_cnt, float run_max, int lane) {
    float* st = d_sumtok + cur_g * H;
    atomicAdd(st + 4*lane + 0,       cs0.x);
    atomicAdd(st + 4*lane + 1,       cs0.y);
    atomicAdd(st + 4*lane + 2,       cs0.z);
    atomicAdd(st + 4*lane + 3,       cs0.w);
    atomicAdd(st + 128 + 4*lane + 0, cs1.x);
    atomicAdd(st + 128 + 4*lane + 1, cs1.y);
    atomicAdd(st + 128 + 4*lane + 2, cs1.z);
    atomicAdd(st + 128 + 4*lane + 3, cs1.w);
    if (lane == 0) {
        atomicAdd(&d_cnt[cur_g], run_cnt);
        atomicMax(&d_gmax[cur_g], f2ord(run_max));
    }
}

__global__ void __launch_bounds__(256, 3)
k_main(const float* __restrict__ et, const int* __restrict__ batch,
       const int* __restrict__ sel, int E, int epw) {
    int wid  = (blockIdx.x * blockDim.x + threadIdx.x) >> 5;
    int lane = threadIdx.x & 31;
    int start = wid * epw;
    if (start >= E) return;
    int end = min(E, start + epw);

    const float4* u4 = (const float4*)d_u;
    float4 ua = u4[lane], ub = u4[lane + 32];

    int    cur_g   = batch[start];
    float4 cs0 = make_float4(0.f, 0.f, 0.f, 0.f);
    float4 cs1 = make_float4(0.f, 0.f, 0.f, 0.f);
    int    run_cnt = 0;
    float  run_max = -3.0e38f;

    int e = start;
    while (e + 1 < end) {
        const float4* r0 = (const float4*)(et + (size_t)e * H);
        const float4* r1 = (const float4*)(et + (size_t)(e + 1) * H);
        float4 a0 = __ldcs(r0 + lane), b0 = __ldcs(r0 + lane + 32);
        float4 a1 = __ldcs(r1 + lane), b1 = __ldcs(r1 + lane + 32);
        int g0 = batch[e], g1 = batch[e + 1];
        int m0 = sel[e],   m1 = sel[e + 1];

        // both dots up front (independent of flush control flow)
        float s0 = a0.x*ua.x + a0.y*ua.y + a0.z*ua.z + a0.w*ua.w
                 + b0.x*ub.x + b0.y*ub.y + b0.z*ub.z + b0.w*ub.w;
        float s1 = a1.x*ua.x + a1.y*ua.y + a1.z*ua.z + a1.w*ua.w
                 + b1.x*ub.x + b1.y*ub.y + b1.z*ub.z + b1.w*ub.w;
        #pragma unroll
        for (int o = 16; o; o >>= 1) {
            s0 += __shfl_xor_sync(0xffffffffu, s0, o);
            s1 += __shfl_xor_sync(0xffffffffu, s1, o);
        }
        // edge 0
        if (g0 != cur_g) {
            flush_run(cur_g, cs0, cs1, run_cnt, run_max, lane);
            cs0 = make_float4(0.f,0.f,0.f,0.f); cs1 = make_float4(0.f,0.f,0.f,0.f);
            run_cnt = 0; run_max = -3.0e38f; cur_g = g0;
        }
        cs0.x += a0.x; cs0.y += a0.y; cs0.z += a0.z; cs0.w += a0.w;
        cs1.x += b0.x; cs1.y += b0.y; cs1.z += b0.z; cs1.w += b0.w;
        {
            float t = s0 + d_qatt[g0];
            t = (t > 0.0f) ? t : 0.2f * t;
            if (m0 == 0) t += 0.5f;
            run_max = fmaxf(run_max, t);
            run_cnt++;
            if (lane == 0) d_att[e] = t;
        }
        // edge 1
        if (g1 != cur_g) {
            flush_run(cur_g, cs0, cs1, run_cnt, run_max, lane);
            cs0 = make_float4(0.f,0.f,0.f,0.f); cs1 = make_float4(0.f,0.f,0.f,0.f);
            run_cnt = 0; run_max = -3.0e38f; cur_g = g1;
        }
        cs0.x += a1.x; cs0.y += a1.y; cs0.z += a1.z; cs0.w += a1.w;
        cs1.x += b1.x; cs1.y += b1.y; cs1.z += b1.z; cs1.w += b1.w;
        {
            float t = s1 + d_qatt[g1];
            t = (t > 0.0f) ? t : 0.2f * t;
            if (m1 == 0) t += 0.5f;
            run_max = fmaxf(run_max, t);
            run_cnt++;
            if (lane == 0) d_att[e + 1] = t;
        }
        e += 2;
    }
    if (e < end) {   // tail edge
        const float4* r0 = (const float4*)(et + (size_t)e * H);
        float4 a0 = __ldcs(r0 + lane), b0 = __ldcs(r0 + lane + 32);
        int g0 = batch[e], m0 = sel[e];
        float s0 = a0.x*ua.x + a0.y*ua.y + a0.z*ua.z + a0.w*ua.w
                 + b0.x*ub.x + b0.y*ub.y + b0.z*ub.z + b0.w*ub.w;
        #pragma unroll
        for (int o = 16; o; o >>= 1) s0 += __shfl_xor_sync(0xffffffffu, s0, o);
        if (g0 != cur_g) {
            flush_run(cur_g, cs0, cs1, run_cnt, run_max, lane);
            cs0 = make_float4(0.f,0.f,0.f,0.f); cs1 = make_float4(0.f,0.f,0.f,0.f);
            run_cnt = 0; run_max = -3.0e38f; cur_g = g0;
        }
        cs0.x += a0.x; cs0.y += a0.y; cs0.z += a0.z; cs0.w += a0.w;
        cs1.x += b0.x; cs1.y += b0.y; cs1.z += b0.z; cs1.w += b0.w;
        float t = s0 + d_qatt[g0];
        t = (t > 0.0f) ? t : 0.2f * t;
        if (m0 == 0) t += 0.5f;
        run_max = fmaxf(run_max, t);
        run_cnt++;
        if (lane == 0) d_att[e] = t;
    }
    flush_run(cur_g, cs0, cs1, run_cnt, run_max, lane);
}

// ---------------- K3: per-graph sum of exp(att - max) over candidates ----------------
__global__ void k_expsum(const int* __restrict__ batch, const int* __restrict__ sel,
                         int E, int chunk) {
    int t = blockIdx.x * blockDim.x + threadIdx.x;
    int start = t * chunk;
    if (start >= E) return;
    int end = min(E, start + chunk);
    int cur_g = batch[start];
    float m = ord2f(d_gmax[cur_g]);
    float acc = 0.0f;
    for (int e = start; e < end; e++) {
        int g = batch[e];
        if (g != cur_g) {
            atomicAdd(&d_gsum[cur_g], acc);
            cur_g = g; m = ord2f(d_gmax[g]); acc = 0.0f;
        }
        if (sel[e] == 0) acc += expf(d_att[e] - m);
    }
    atomicAdd(&d_gsum[cur_g], acc);
}

// ---------------- K4: edge_logits (log-domain, no exp) ----------------
__global__ void k_logits(const int* __restrict__ batch, const int* __restrict__ sel,
                         float* __restrict__ out, int E) {
    int e = blockIdx.x * blockDim.x + threadIdx.x;
    if (e >= E) return;
    int g = batch[e];
    float r;
    if (sel[e] == 0) {
        float m = ord2f(d_gmax[g]);
        float ls = logf(fmaxf(d_gsum[g], FLT_EPSILON));
        r = fmaxf(d_att[e] - m - ls, LOGEPS);
    } else {
        r = LOGEPS;
    }
    out[e] = r;
}

// ---------------- K5: pooled GEMM + stop head (GT graphs per block) ----------------
__global__ void __launch_bounds__(256)
k_head(const float* __restrict__ qt, const float* __restrict__ We,
       const float* __restrict__ lng, const float* __restrict__ lnb,
       const float* __restrict__ W1, const float* __restrict__ b1,
       const float* __restrict__ W2, const float* __restrict__ b2,
       float* __restrict__ out_stop, float* __restrict__ out_pool) {
    __shared__ float spool[GT][H];     // 8 KB
    __shared__ float sxn[GT][H2];      // 16 KB
    __shared__ float sred[8][GT];
    __shared__ float smu[GT], sinv[GT];
    int g0 = blockIdx.x * GT;
    int j = threadIdx.x;
    int w = j >> 5, lane = j & 31;

    #pragma unroll
    for (int g = 0; g < GT; g++) spool[g][j] = d_sumtok[(g0 + g) * H + j];
    __syncthreads();

    // pooled[g][j] = dot(We row j, spool[g]) / cnt[g]
    float pj[GT];
    #pragma unroll
    for (int g = 0; g < GT; g++) pj[g] = 0.0f;
    const float4* wr = (const float4*)(We + j * H);
    for (int k = 0; k < H / 4; k++) {
        float4 wv = wr[k];
        #pragma unroll
        for (int g = 0; g < GT; g++) {
            float4 x = ((const float4*)spool[g])[k];
            pj[g] = fmaf(wv.x, x.x, pj[g]); pj[g] = fmaf(wv.y, x.y, pj[g]);
            pj[g] = fmaf(wv.z, x.z, pj[g]); pj[g] = fmaf(wv.w, x.w, pj[g]);
        }
    }
    float x1[GT];
    #pragma unroll
    for (int g = 0; g < GT; g++) {
        float c = (float)max(d_cnt[g0 + g], 1);
        pj[g] /= c;
        out_pool[(g0 + g) * H + j] = pj[g];
        x1[g] = qt[(g0 + g) * H + j];
    }

    // LayerNorm over 512: mean
    #pragma unroll
    for (int g = 0; g < GT; g++) {
        float v = pj[g] + x1[g];
        #pragma unroll
        for (int o = 16; o; o >>= 1) v += __shfl_xor_sync(0xffffffffu, v, o);
        if (lane == 0) sred[w][g] = v;
    }
    __syncthreads();
    if (j < GT) {
        float tot = 0.0f;
        #pragma unroll
        for (int r = 0; r < 8; r++) tot += sred[r][j];
        smu[j] = tot * (1.0f / 512.0f);
    }
    __syncthreads();
    // variance
    #pragma unroll
    for (int g = 0; g < GT; g++) {
        float d0 = pj[g] - smu[g], d1 = x1[g] - smu[g];
        float v = d0 * d0 + d1 * d1;
        #pragma unroll
        for (int o = 16; o; o >>= 1) v += __shfl_xor_sync(0xffffffffu, v, o);
        if (lane == 0) sred[w][g] = v;
    }
    __syncthreads();
    if (j < GT) {
        float var = 0.0f;
        #pragma unroll
        for (int r = 0; r < 8; r++) var += sred[r][j];
        sinv[j] = rsqrtf(var * (1.0f / 512.0f) + 1e-5f);
    }
    __syncthreads();
    float g0v = lng[j], g1v = lng[H + j], b0v = lnb[j], b1v = lnb[H + j];
    #pragma unroll
    for (int g = 0; g < GT; g++) {
        sxn[g][j]     = (pj[g] - smu[g]) * sinv[g] * g0v + b0v;
        sxn[g][H + j] = (x1[g] - smu[g]) * sinv[g] * g1v + b1v;
    }
    __syncthreads();

    // h1[g][j] = GELU(b1[j] + dot(W1 row j (512), sxn[g]))
    float hh[GT];
    float bb = b1[j];
    #pragma unroll
    for (int g = 0; g < GT; g++) hh[g] = bb;
    const float4* w1r = (const float4*)(W1 + j * H2);
    for (int k = 0; k < H2 / 4; k++) {
        float4 wv = w1r[k];
        #pragma unroll
        for (int g = 0; g < GT; g++) {
            float4 x = ((const float4*)sxn[g])[k];
            hh[g] = fmaf(wv.x, x.x, hh[g]); hh[g] = fmaf(wv.y, x.y, hh[g]);
            hh[g] = fmaf(wv.z, x.z, hh[g]); hh[g] = fmaf(wv.w, x.w, hh[g]);
        }
    }
    float w2j = W2[j];
    #pragma unroll
    for (int g = 0; g < GT; g++) {
        float h = hh[g];
        h = 0.5f * h * (1.0f + erff(h * 0.70710678118654752f));
        float v = h * w2j;
        #pragma unroll
        for (int o = 16; o; o >>= 1) v += __shfl_xor_sync(0xffffffffu, v, o);
        if (lane == 0) sred[w][g] = v;
    }
    __syncthreads();
    if (j < GT) {
        float st = 0.0f;
        #pragma unroll
        for (int r = 0; r < 8; r++) st += sred[r][j];
        out_stop[g0 + j] = st + b2[0];
    }
}

// ---------------- launch ----------------
extern "C" void kernel_launch(void* const* d_in, const int* in_sizes, int n_in,
                              void* d_out, int out_size) {
    const float* edge_tokens     = (const float*)d_in[0];
    const float* question_tokens = (const float*)d_in[1];
    const int*   edge_batch      = (const int*)d_in[2];
    const int*   selected_mask   = (const int*)d_in[3];
    const float* W_edge          = (const float*)d_in[4];
    const float* W_query         = (const float*)d_in[5];
    const float* att_vec         = (const float*)d_in[6];
    const float* ln_g            = (const float*)d_in[7];
    const float* ln_b            = (const float*)d_in[8];
    const float* W1              = (const float*)d_in[9];
    const float* b1              = (const float*)d_in[10];
    const float* W2              = (const float*)d_in[11];
    const float* b2              = (const float*)d_in[12];

    int E = in_sizes[2];
    float* out      = (float*)d_out;
    float* out_edge = out;             // [E]
    float* out_stop = out + E;         // [G]
    float* out_pool = out + E + G_;    // [G, H]

    // K1: u, v (8 blocks)
    k_uv<<<8, 256>>>(W_edge, W_query, att_vec);
    // K1b: qatt + scratch init (256 blocks x 32)
    k_qatt<<<G_, 32>>>(question_tokens);
    // K2: main streaming pass — exactly 3 blocks per SM (148*3 = 444)
    {
        int blocks = 444, threads = 256;
        int warps = blocks * threads / 32;        // 3552
        int epw = (E + warps - 1) / warps;        // 141
        k_main<<<blocks, threads>>>(edge_tokens, edge_batch, selected_mask, E, epw);
    }
    // K3: exp sums
    {
        int chunk = 32;
        int nthreads = (E + chunk - 1) / chunk;
        k_expsum<<<(nthreads + 255) / 256, 256>>>(edge_batch, selected_mask, E, chunk);
    }
    // K4: edge logits
    k_logits<<<(E + 255) / 256, 256>>>(edge_batch, selected_mask, out_edge, E);
    // K5: pooled + stop head (8 graphs per block)
    k_head<<<G_ / GT, 256>>>(question_tokens, W_edge, ln_g, ln_b, W1, b1, W2, b2,
                             out_stop, out_pool);
}

// round 6
// speedup vs baseline: 1.5362x; 1.1131x over previous
#include <cuda_runtime.h>
#include <math.h>
#include <float.h>

#define H 256
#define G_ 256
#define H2 512
#define E_MAX 524288
#define GT 8                            // graphs per block in k_head
#define RUN_CAP 8192
#define LOGEPS -15.942385152878742f     // logf(FLT_EPSILON)

// ---------------- scratch (static device globals; no allocation) ----------------
__device__ float    d_att[E_MAX];      // att score per edge (candidates); -1e38 for selected
__device__ float    d_sumtok[G_ * H];  // segment sum of edge_tokens
__device__ int      d_cnt[G_];         // edges per graph
__device__ unsigned d_gmax[G_];        // ordered-uint encoded segment max
__device__ float    d_off[G_];         // gmax + log(gsum) per graph
__device__ float    d_u[H];            // att_vec @ W_edge
__device__ float    d_v[H];            // att_vec @ W_query
__device__ float    d_qatt[G_];        // question_tokens @ v
__device__ int      d_nrun;            // run record counter
__device__ int      d_rg[RUN_CAP];     // run graph id
__device__ float    d_rm[RUN_CAP];     // run max
__device__ float    d_rs[RUN_CAP];     // run expsum (relative to run max)

// monotone float<->uint map for atomicMax on floats (handles negatives)
__device__ __forceinline__ unsigned f2ord(float f) {
    unsigned b = __float_as_uint(f);
    return (b & 0x80000000u) ? ~b : (b | 0x80000000u);
}
__device__ __forceinline__ float ord2f(unsigned u) {
    unsigned b = (u & 0x80000000u) ? (u & 0x7fffffffu) : ~u;
    return __uint_as_float(b);
}

// ---------------- K1: u = att_vec @ W_edge, v = att_vec @ W_query (8 blocks) ----
__global__ void k_uv(const float* __restrict__ We, const float* __restrict__ Wq,
                     const float* __restrict__ av) {
    __shared__ float sa[H];
    __shared__ float ru[8][32], rv[8][32];
    int tx = threadIdx.x & 31, ty = threadIdx.x >> 5;
    sa[threadIdx.x] = av[threadIdx.x];
    __syncthreads();
    int col = blockIdx.x * 32 + tx;
    float u = 0.0f, v = 0.0f;
    #pragma unroll 4
    for (int j = ty; j < H; j += 8) {
        float a = sa[j];
        u = fmaf(a, We[j * H + col], u);
        v = fmaf(a, Wq[j * H + col], v);
    }
    ru[ty][tx] = u; rv[ty][tx] = v;
    __syncthreads();
    if (ty == 0) {
        float su = 0.0f, sv = 0.0f;
        #pragma unroll
        for (int r = 0; r < 8; r++) { su += ru[r][tx]; sv += rv[r][tx]; }
        d_u[col] = su; d_v[col] = sv;
    }
}

// ---------------- K1b: qatt[g] = question_tokens[g] . v   + scratch init ----------
__global__ void k_qatt(const float* __restrict__ qt) {
    int g = blockIdx.x, lane = threadIdx.x;
    float4 z = make_float4(0.f, 0.f, 0.f, 0.f);
    ((float4*)d_sumtok)[g * 64 + lane]      = z;
    ((float4*)d_sumtok)[g * 64 + 32 + lane] = z;
    if (lane == 0) { d_cnt[g] = 0; d_gmax[g] = 0u; }
    if (g == 0 && lane == 0) d_nrun = 0;
    const float4* q4 = (const float4*)(qt + g * H);
    const float4* v4 = (const float4*)d_v;
    float4 a = q4[lane], b = q4[lane + 32];
    float4 va = v4[lane], vb = v4[lane + 32];
    float s = a.x*va.x + a.y*va.y + a.z*va.z + a.w*va.w
            + b.x*vb.x + b.y*vb.y + b.z*vb.z + b.w*vb.w;
    #pragma unroll
    for (int o = 16; o; o >>= 1) s += __shfl_xor_sync(0xffffffffu, s, o);
    if (lane == 0) d_qatt[g] = s;
}

// ---------------- K2: main streaming pass (online run softmax) ----------------
__device__ __forceinline__ void flush_run(int cur_g, float4 cs0, float4 cs1,
                                          int run_cnt, float run_max, float run_sum,
                                          int lane) {
    float* st = d_sumtok + cur_g * H;
    atomicAdd(st + 4*lane + 0,       cs0.x);
    atomicAdd(st + 4*lane + 1,       cs0.y);
    atomicAdd(st + 4*lane + 2,       cs0.z);
    atomicAdd(st + 4*lane + 3,       cs0.w);
    atomicAdd(st + 128 + 4*lane + 0, cs1.x);
    atomicAdd(st + 128 + 4*lane + 1, cs1.y);
    atomicAdd(st + 128 + 4*lane + 2, cs1.z);
    atomicAdd(st + 128 + 4*lane + 3, cs1.w);
    if (lane == 0) {
        atomicAdd(&d_cnt[cur_g], run_cnt);
        atomicMax(&d_gmax[cur_g], f2ord(run_max));
        int idx = atomicAdd(&d_nrun, 1);
        if (idx < RUN_CAP) {
            d_rg[idx] = cur_g; d_rm[idx] = run_max; d_rs[idx] = run_sum;
        }
    }
}

__global__ void __launch_bounds__(256, 4)
k_main(const float* __restrict__ et, const int* __restrict__ batch,
       const int* __restrict__ sel, int E, int epw) {
    int wid  = (blockIdx.x * blockDim.x + threadIdx.x) >> 5;
    int lane = threadIdx.x & 31;
    int start = wid * epw;
    if (start >= E) return;
    int end = min(E, start + epw);

    const float4* u4 = (const float4*)d_u;
    float4 ua = u4[lane], ub = u4[lane + 32];

    int    cur_g   = batch[start];
    float4 cs0 = make_float4(0.f, 0.f, 0.f, 0.f);
    float4 cs1 = make_float4(0.f, 0.f, 0.f, 0.f);
    int    run_cnt = 0;
    float  run_max = -3.0e38f;
    float  run_sum = 0.0f;

    int e = start;
    while (e + 1 < end) {
        const float4* r0 = (const float4*)(et + (size_t)e * H);
        const float4* r1 = (const float4*)(et + (size_t)(e + 1) * H);
        float4 a0 = __ldcs(r0 + lane), b0 = __ldcs(r0 + lane + 32);
        float4 a1 = __ldcs(r1 + lane), b1 = __ldcs(r1 + lane + 32);
        int g0 = batch[e], g1 = batch[e + 1];
        int m0 = sel[e],   m1 = sel[e + 1];

        float s0 = a0.x*ua.x + a0.y*ua.y + a0.z*ua.z + a0.w*ua.w
                 + b0.x*ub.x + b0.y*ub.y + b0.z*ub.z + b0.w*ub.w;
        float s1 = a1.x*ua.x + a1.y*ua.y + a1.z*ua.z + a1.w*ua.w
                 + b1.x*ub.x + b1.y*ub.y + b1.z*ub.z + b1.w*ub.w;
        #pragma unroll
        for (int o = 16; o; o >>= 1) {
            s0 += __shfl_xor_sync(0xffffffffu, s0, o);
            s1 += __shfl_xor_sync(0xffffffffu, s1, o);
        }
        // edge 0
        if (g0 != cur_g) {
            flush_run(cur_g, cs0, cs1, run_cnt, run_max, run_sum, lane);
            cs0 = make_float4(0.f,0.f,0.f,0.f); cs1 = make_float4(0.f,0.f,0.f,0.f);
            run_cnt = 0; run_max = -3.0e38f; run_sum = 0.0f; cur_g = g0;
        }
        cs0.x += a0.x; cs0.y += a0.y; cs0.z += a0.z; cs0.w += a0.w;
        cs1.x += b0.x; cs1.y += b0.y; cs1.z += b0.z; cs1.w += b0.w;
        {
            float t = s0 + d_qatt[g0];
            t = (t > 0.0f) ? t : 0.2f * t;
            if (m0 == 0) t += 0.5f;
            float nm = fmaxf(run_max, t);
            run_sum = run_sum * expf(run_max - nm)
                    + ((m0 == 0) ? expf(t - nm) : 0.0f);
            run_max = nm;
            run_cnt++;
            if (lane == 0) d_att[e] = (m0 == 0) ? t : -1.0e38f;
        }
        // edge 1
        if (g1 != cur_g) {
            flush_run(cur_g, cs0, cs1, run_cnt, run_max, run_sum, lane);
            cs0 = make_float4(0.f,0.f,0.f,0.f); cs1 = make_float4(0.f,0.f,0.f,0.f);
            run_cnt = 0; run_max = -3.0e38f; run_sum = 0.0f; cur_g = g1;
        }
        cs0.x += a1.x; cs0.y += a1.y; cs0.z += a1.z; cs0.w += a1.w;
        cs1.x += b1.x; cs1.y += b1.y; cs1.z += b1.z; cs1.w += b1.w;
        {
            float t = s1 + d_qatt[g1];
            t = (t > 0.0f) ? t : 0.2f * t;
            if (m1 == 0) t += 0.5f;
            float nm = fmaxf(run_max, t);
            run_sum = run_sum * expf(run_max - nm)
                    + ((m1 == 0) ? expf(t - nm) : 0.0f);
            run_max = nm;
            run_cnt++;
            if (lane == 0) d_att[e + 1] = (m1 == 0) ? t : -1.0e38f;
        }
        e += 2;
    }
    if (e < end) {   // tail edge
        const float4* r0 = (const float4*)(et + (size_t)e * H);
        float4 a0 = __ldcs(r0 + lane), b0 = __ldcs(r0 + lane + 32);
        int g0 = batch[e], m0 = sel[e];
        float s0 = a0.x*ua.x + a0.y*ua.y + a0.z*ua.z + a0.w*ua.w
                 + b0.x*ub.x + b0.y*ub.y + b0.z*ub.z + b0.w*ub.w;
        #pragma unroll
        for (int o = 16; o; o >>= 1) s0 += __shfl_xor_sync(0xffffffffu, s0, o);
        if (g0 != cur_g) {
            flush_run(cur_g, cs0, cs1, run_cnt, run_max, run_sum, lane);
            cs0 = make_float4(0.f,0.f,0.f,0.f); cs1 = make_float4(0.f,0.f,0.f,0.f);
            run_cnt = 0; run_max = -3.0e38f; run_sum = 0.0f; cur_g = g0;
        }
        cs0.x += a0.x; cs0.y += a0.y; cs0.z += a0.z; cs0.w += a0.w;
        cs1.x += b0.x; cs1.y += b0.y; cs1.z += b0.z; cs1.w += b0.w;
        float t = s0 + d_qatt[g0];
        t = (t > 0.0f) ? t : 0.2f * t;
        if (m0 == 0) t += 0.5f;
        float nm = fmaxf(run_max, t);
        run_sum = run_sum * expf(run_max - nm)
                + ((m0 == 0) ? expf(t - nm) : 0.0f);
        run_max = nm;
        run_cnt++;
        if (lane == 0) d_att[e] = (m0 == 0) ? t : -1.0e38f;
    }
    flush_run(cur_g, cs0, cs1, run_cnt, run_max, run_sum, lane);
}

// ---------------- K3: combine run records -> d_off[g] (single block) ------------
__global__ void k_comb() {
    __shared__ float ssum[G_];
    int t = threadIdx.x;
    if (t < G_) ssum[t] = 0.0f;
    __syncthreads();
    int n = d_nrun;
    if (n > RUN_CAP) n = RUN_CAP;
    for (int i = t; i < n; i += blockDim.x) {
        int g = d_rg[i];
        float m = ord2f(d_gmax[g]);
        atomicAdd(&ssum[g], d_rs[i] * expf(d_rm[i] - m));
    }
    __syncthreads();
    if (t < G_) d_off[t] = ord2f(d_gmax[t]) + logf(fmaxf(ssum[t], FLT_EPSILON));
}

// ---------------- K4: edge_logits (vectorized x4, no sel read) ----------------
__global__ void k_logits(const int* __restrict__ batch, float* __restrict__ out,
                         int E4) {
    int i = blockIdx.x * blockDim.x + threadIdx.x;
    if (i >= E4) return;
    int4   g = ((const int4*)batch)[i];
    float4 a = ((const float4*)d_att)[i];
    float4 r;
    r.x = fmaxf(a.x - d_off[g.x], LOGEPS);
    r.y = fmaxf(a.y - d_off[g.y], LOGEPS);
    r.z = fmaxf(a.z - d_off[g.z], LOGEPS);
    r.w = fmaxf(a.w - d_off[g.w], LOGEPS);
    ((float4*)out)[i] = r;
}
__global__ void k_logits_tail(const int* __restrict__ batch, float* __restrict__ out,
                              int start, int E) {
    int e = start + blockIdx.x * blockDim.x + threadIdx.x;
    if (e >= E) return;
    out[e] = fmaxf(d_att[e] - d_off[batch[e]], LOGEPS);
}

// ---------------- K5: pooled GEMM + stop head (GT graphs per block) ----------------
__global__ void __launch_bounds__(256)
k_head(const float* __restrict__ qt, const float* __restrict__ We,
       const float* __restrict__ lng, const float* __restrict__ lnb,
       const float* __restrict__ W1, const float* __restrict__ b1,
       const float* __restrict__ W2, const float* __restrict__ b2,
       float* __restrict__ out_stop, float* __restrict__ out_pool) {
    __shared__ float spool[GT][H];
    __shared__ float sxn[GT][H2];
    __shared__ float sred[8][GT];
    __shared__ float smu[GT], sinv[GT];
    int g0 = blockIdx.x * GT;
    int j = threadIdx.x;
    int w = j >> 5, lane = j & 31;

    #pragma unroll
    for (int g = 0; g < GT; g++) spool[g][j] = d_sumtok[(g0 + g) * H + j];
    __syncthreads();

    float pj[GT];
    #pragma unroll
    for (int g = 0; g < GT; g++) pj[g] = 0.0f;
    const float4* wr = (const float4*)(We + j * H);
    for (int k = 0; k < H / 4; k++) {
        float4 wv = wr[k];
        #pragma unroll
        for (int g = 0; g < GT; g++) {
            float4 x = ((const float4*)spool[g])[k];
            pj[g] = fmaf(wv.x, x.x, pj[g]); pj[g] = fmaf(wv.y, x.y, pj[g]);
            pj[g] = fmaf(wv.z, x.z, pj[g]); pj[g] = fmaf(wv.w, x.w, pj[g]);
        }
    }
    float x1[GT];
    #pragma unroll
    for (int g = 0; g < GT; g++) {
        float c = (float)max(d_cnt[g0 + g], 1);
        pj[g] /= c;
        out_pool[(g0 + g) * H + j] = pj[g];
        x1[g] = qt[(g0 + g) * H + j];
    }

    #pragma unroll
    for (int g = 0; g < GT; g++) {
        float v = pj[g] + x1[g];
        #pragma unroll
        for (int o = 16; o; o >>= 1) v += __shfl_xor_sync(0xffffffffu, v, o);
        if (lane == 0) sred[w][g] = v;
    }
    __syncthreads();
    if (j < GT) {
        float tot = 0.0f;
        #pragma unroll
        for (int r = 0; r < 8; r++) tot += sred[r][j];
        smu[j] = tot * (1.0f / 512.0f);
    }
    __syncthreads();
    #pragma unroll
    for (int g = 0; g < GT; g++) {
        float d0 = pj[g] - smu[g], d1 = x1[g] - smu[g];
        float v = d0 * d0 + d1 * d1;
        #pragma unroll
        for (int o = 16; o; o >>= 1) v += __shfl_xor_sync(0xffffffffu, v, o);
        if (lane == 0) sred[w][g] = v;
    }
    __syncthreads();
    if (j < GT) {
        float var = 0.0f;
        #pragma unroll
        for (int r = 0; r < 8; r++) var += sred[r][j];
        sinv[j] = rsqrtf(var * (1.0f / 512.0f) + 1e-5f);
    }
    __syncthreads();
    float g0v = lng[j], g1v = lng[H + j], b0v = lnb[j], b1v = lnb[H + j];
    #pragma unroll
    for (int g = 0; g < GT; g++) {
        sxn[g][j]     = (pj[g] - smu[g]) * sinv[g] * g0v + b0v;
        sxn[g][H + j] = (x1[g] - smu[g]) * sinv[g] * g1v + b1v;
    }
    __syncthreads();

    float hh[GT];
    float bb = b1[j];
    #pragma unroll
    for (int g = 0; g < GT; g++) hh[g] = bb;
    const float4* w1r = (const float4*)(W1 + j * H2);
    for (int k = 0; k < H2 / 4; k++) {
        float4 wv = w1r[k];
        #pragma unroll
        for (int g = 0; g < GT; g++) {
            float4 x = ((const float4*)sxn[g])[k];
            hh[g] = fmaf(wv.x, x.x, hh[g]); hh[g] = fmaf(wv.y, x.y, hh[g]);
            hh[g] = fmaf(wv.z, x.z, hh[g]); hh[g] = fmaf(wv.w, x.w, hh[g]);
        }
    }
    float w2j = W2[j];
    #pragma unroll
    for (int g = 0; g < GT; g++) {
        float h = hh[g];
        h = 0.5f * h * (1.0f + erff(h * 0.70710678118654752f));
        float v = h * w2j;
        #pragma unroll
        for (int o = 16; o; o >>= 1) v += __shfl_xor_sync(0xffffffffu, v, o);
        if (lane == 0) sred[w][g] = v;
    }
    __syncthreads();
    if (j < GT) {
        float st = 0.0f;
        #pragma unroll
        for (int r = 0; r < 8; r++) st += sred[r][j];
        out_stop[g0 + j] = st + b2[0];
    }
}

// ---------------- launch ----------------
extern "C" void kernel_launch(void* const* d_in, const int* in_sizes, int n_in,
                              void* d_out, int out_size) {
    const float* edge_tokens     = (const float*)d_in[0];
    const float* question_tokens = (const float*)d_in[1];
    const int*   edge_batch      = (const int*)d_in[2];
    const int*   selected_mask   = (const int*)d_in[3];
    const float* W_edge          = (const float*)d_in[4];
    const float* W_query         = (const float*)d_in[5];
    const float* att_vec         = (const float*)d_in[6];
    const float* ln_g            = (const float*)d_in[7];
    const float* ln_b            = (const float*)d_in[8];
    const float* W1              = (const float*)d_in[9];
    const float* b1              = (const float*)d_in[10];
    const float* W2              = (const float*)d_in[11];
    const float* b2              = (const float*)d_in[12];

    int E = in_sizes[2];
    float* out      = (float*)d_out;
    float* out_edge = out;             // [E]
    float* out_stop = out + E;         // [G]
    float* out_pool = out + E + G_;    // [G, H]

    k_uv<<<8, 256>>>(W_edge, W_query, att_vec);
    k_qatt<<<G_, 32>>>(question_tokens);
    // main pass: exactly 4 blocks per SM (148*4 = 592)
    {
        int blocks = 592, threads = 256;
        int warps = blocks * threads / 32;        // 4736
        int epw = (E + warps - 1) / warps;
        k_main<<<blocks, threads>>>(edge_tokens, edge_batch, selected_mask, E, epw);
    }
    k_comb<<<1, 1024>>>();
    {
        int E4 = E / 4;
        if (E4 > 0)
            k_logits<<<(E4 + 255) / 256, 256>>>(edge_batch, out_edge, E4);
        int rem = E - E4 * 4;
        if (rem > 0)
            k_logits_tail<<<1, 256>>>(edge_batch, out_edge, E4 * 4, E);
    }
    k_head<<<G_ / GT, 256>>>(question_tokens, W_edge, ln_g, ln_b, W1, b1, W2, b2,
                             out_stop, out_pool);
}